// round 4
// baseline (speedup 1.0000x reference)
#include <cuda_runtime.h>
#include <cstdint>

// ---------------- problem constants ----------------
#define NN      65536
#define CC      256
#define BB      8
#define EMBD    512
#define NET     7
#define EE      458752
#define WROW    263
#define EPSV    1e-5f

// ---------------- device scratch ----------------
// A in MMA fragment layout: [mt (4096)][kt (32)][lane (32)][4 floats]
__device__ __align__(256) float    g_hA[(size_t)NN * CC];
// B in MMA fragment layout: [t][nt (32)][kt (32)][lane (32)][2 floats]
__device__ __align__(256) float    g_WtB[(size_t)NET * 32 * 32 * 32 * 2];
__device__ __align__(256) float    g_Y[(size_t)NET * NN * CC];
__device__ __align__(256) float    g_out1[(size_t)NN * CC];
__device__ float    g_S1[BB * CC];
__device__ float    g_S2[BB * CC];
__device__ float    g_cnt[BB];
__device__ float    g_mg[BB * 32];
__device__ float    g_istd[BB * 32];
__device__ __align__(256) float    g_emb[BB * CC];
__device__ int      g_deg[NN];
__device__ int      g_off[NN + 1];
__device__ int      g_cur[NN];
__device__ unsigned g_epack[EE];

// ---------------- helpers ----------------
__device__ __forceinline__ unsigned f2tf32(float f) {
    unsigned u;
    asm("cvt.rna.tf32.f32 %0, %1;" : "=r"(u) : "f"(f));
    return u;
}

__device__ __forceinline__ float silu(float y) {
    return y / (1.f + __expf(-y));
}

__device__ __forceinline__ uint32_t smem_u32(const void* p) {
    uint32_t a;
    asm("{ .reg .u64 t; cvta.to.shared.u64 t, %1; cvt.u32.u64 %0, t; }" : "=r"(a) : "l"(p));
    return a;
}

__device__ __forceinline__ void cp16(uint32_t dst, const void* src) {
    asm volatile("cp.async.cg.shared.global [%0], [%1], 16;\n" :: "r"(dst), "l"(src));
}
__device__ __forceinline__ void cp_commit() { asm volatile("cp.async.commit_group;\n" ::: "memory"); }
__device__ __forceinline__ void cp_wait1()  { asm volatile("cp.async.wait_group 1;\n" ::: "memory"); }
__device__ __forceinline__ void cp_wait0()  { asm volatile("cp.async.wait_group 0;\n" ::: "memory"); }

__device__ __forceinline__ void mma_tf32(float c[4], unsigned a0, unsigned a1,
                                         unsigned a2, unsigned a3,
                                         unsigned b0, unsigned b1) {
    asm volatile(
        "mma.sync.aligned.m16n8k8.row.col.f32.tf32.tf32.f32 "
        "{%0,%1,%2,%3}, {%4,%5,%6,%7}, {%8,%9}, {%0,%1,%2,%3};\n"
        : "+f"(c[0]), "+f"(c[1]), "+f"(c[2]), "+f"(c[3])
        : "r"(a0), "r"(a1), "r"(a2), "r"(a3), "r"(b0), "r"(b1));
}

// ---------------- CSR / stats kernels ----------------

__global__ void k_zero_all() {
    int i = blockIdx.x * blockDim.x + threadIdx.x;
    if (i < NN)      g_deg[i] = 0;
    if (i < BB * CC) { g_S1[i] = 0.f; g_S2[i] = 0.f; }
    if (i < BB)      g_cnt[i] = 0.f;
}

__global__ void k_zero_stats() {
    int i = blockIdx.x * blockDim.x + threadIdx.x;
    if (i < BB * CC) { g_S1[i] = 0.f; g_S2[i] = 0.f; }
}

__global__ void k_deg(const int* __restrict__ ei) {
    int e = blockIdx.x * blockDim.x + threadIdx.x;
    if (e < EE) atomicAdd(&g_deg[ei[e]], 1);
}

__global__ void k_scan() {
    __shared__ int ps[1024];
    int t = threadIdx.x;
    int s = 0;
#pragma unroll 8
    for (int i = 0; i < 64; i++) s += g_deg[t * 64 + i];
    ps[t] = s;
    __syncthreads();
    for (int off = 1; off < 1024; off <<= 1) {
        int v = (t >= off) ? ps[t - off] : 0;
        __syncthreads();
        ps[t] += v;
        __syncthreads();
    }
    int run = (t == 0) ? 0 : ps[t - 1];
    for (int i = 0; i < 64; i++) {
        int d = g_deg[t * 64 + i];
        g_off[t * 64 + i] = run;
        g_cur[t * 64 + i] = run;
        run += d;
    }
    if (t == 1023) g_off[NN] = run;
}

__global__ void k_fill(const int* __restrict__ ei, const int* __restrict__ et,
                       const int* __restrict__ ntp) {
    int e = blockIdx.x * blockDim.x + threadIdx.x;
    if (e >= EE) return;
    int r = ei[e];
    int c = ei[EE + e];
    int t = et[e];
    int nt = ntp[c];
    int pos = atomicAdd(&g_cur[r], 1);
    g_epack[pos] = (unsigned)c | ((unsigned)t << 16) | ((unsigned)nt << 19);
}

__global__ void k_emb(const float* __restrict__ emb, const float* __restrict__ ew,
                      const float* __restrict__ eb) {
    __shared__ float se[EMBD];
    int b = blockIdx.x;
    int j = threadIdx.x;
    for (int k = j; k < EMBD; k += 256) se[k] = silu(emb[b * EMBD + k]);
    __syncthreads();
    float acc = eb[j];
#pragma unroll 8
    for (int k = 0; k < EMBD; k++) acc = fmaf(se[k], ew[k * CC + j], acc);
    g_emb[b * CC + j] = acc;
}

__global__ void k_stats(const float* __restrict__ src, int use_out1,
                        const int* __restrict__ bid, int do_cnt) {
    const float* s = use_out1 ? g_out1 : src;
    int c = threadIdx.x;
    int r0 = blockIdx.x * 64;
    float s1 = 0.f, s2 = 0.f;
    int cb = bid[r0];
    int cl = 0;
    for (int i = 0; i < 64; i++) {
        int r = r0 + i;
        int b = bid[r];
        if (b != cb) {
            atomicAdd(&g_S1[cb * CC + c], s1);
            atomicAdd(&g_S2[cb * CC + c], s2);
            if (do_cnt && c == 0) atomicAdd(&g_cnt[cb], (float)cl);
            s1 = 0.f; s2 = 0.f; cl = 0; cb = b;
        }
        float v = s[(size_t)r * CC + c];
        s1 += v;
        s2 = fmaf(v, v, s2);
        cl++;
    }
    atomicAdd(&g_S1[cb * CC + c], s1);
    atomicAdd(&g_S2[cb * CC + c], s2);
    if (do_cnt && c == 0) atomicAdd(&g_cnt[cb], (float)cl);
}

__global__ void k_fin() {
    int t = threadIdx.x;
    int b = t >> 5, g = t & 31;
    float gs1 = 0.f, gs2 = 0.f;
#pragma unroll
    for (int i = 0; i < 8; i++) {
        gs1 += g_S1[b * CC + g * 8 + i];
        gs2 += g_S2[b * CC + g * 8 + i];
    }
    float n = g_cnt[b] * 8.f;
    float inv = 1.f / (n + EPSV);
    float m = gs1 * inv;
    float var = (gs2 - 2.f * m * gs1 + n * m * m) * inv;
    g_mg[b * 32 + g] = m;
    g_istd[b * 32 + g] = rsqrtf(var + EPSV);
}

// norm + silu + tf32-round, written into A-fragment layout.
// block = m-tile (16 rows), 256 threads.
__global__ void k_norm(const float* __restrict__ src, int use_out1,
                       const int* __restrict__ bid, const float* __restrict__ w,
                       const float* __restrict__ bbv) {
    __shared__ float s[16 * 256];
    __shared__ int   rb[16];
    const float* sp = use_out1 ? g_out1 : src;
    int mt = blockIdx.x;
    int tid = threadIdx.x;

    // stage 16 rows coalesced
#pragma unroll
    for (int j = 0; j < 4; j++) {
        int q = j * 256 + tid;            // 0..1023 float4 slots
        int row = q >> 6, cv = (q & 63) * 4;
        *(float4*)&s[row * 256 + cv] = *(const float4*)(sp + (size_t)(mt * 16 + row) * CC + cv);
    }
    if (tid < 16) rb[tid] = bid[mt * 16 + tid];
    __syncthreads();

#pragma unroll
    for (int it = 0; it < 4; it++) {
        int idx = it * 256 + tid;         // 0..1023 = kt*32 + lane
        int kt = idx >> 5, lane = idx & 31;
        int gid = lane >> 2, tig = lane & 3;
        int c0 = kt * 8 + tig, c1 = c0 + 4;
        int b0 = rb[gid], b1 = rb[gid + 8];
        float m0 = g_mg[b0 * 32 + kt], i0 = g_istd[b0 * 32 + kt];
        float m1 = g_mg[b1 * 32 + kt], i1 = g_istd[b1 * 32 + kt];
        float w0 = w[c0], w1 = w[c1], q0 = bbv[c0], q1 = bbv[c1];
        float v00 = silu((s[gid * 256 + c0] - m0) * i0 * w0 + q0);
        float v10 = silu((s[(gid + 8) * 256 + c0] - m1) * i1 * w0 + q0);
        float v01 = silu((s[gid * 256 + c1] - m0) * i0 * w1 + q1);
        float v11 = silu((s[(gid + 8) * 256 + c1] - m1) * i1 * w1 + q1);
        float4 o;
        o.x = __uint_as_float(f2tf32(v00));
        o.y = __uint_as_float(f2tf32(v10));
        o.z = __uint_as_float(f2tf32(v01));
        o.w = __uint_as_float(f2tf32(v11));
        *(float4*)&g_hA[(((size_t)mt * 32 + kt) * 32 + lane) * 4] = o;
    }
}

// W[t][k][n] (dense 256 rows per type) -> B-fragment layout, tf32-rounded
__global__ void k_wt(const float* __restrict__ W) {
    int g = blockIdx.x * blockDim.x + threadIdx.x;
    if (g >= NET * 32 * 32 * 32) return;
    int lane = g & 31, kt = (g >> 5) & 31, nt = (g >> 10) & 31, t = g >> 15;
    int gid = lane >> 2, tig = lane & 3;
    int n = nt * 8 + gid;
    float b0 = W[(size_t)(t * WROW + kt * 8 + tig) * CC + n];
    float b1 = W[(size_t)(t * WROW + kt * 8 + tig + 4) * CC + n];
    float2 o;
    o.x = __uint_as_float(f2tf32(b0));
    o.y = __uint_as_float(f2tf32(b1));
    *(float2*)&g_WtB[(size_t)g * 2] = o;
}

// -------- tf32 mma.sync GEMM, fragment-major smem, cp.async double buffer ----
// CTA 128x128, K=256 in four K=64 chunks. smem: A0|A1|B0|B1 each 32KB.
#define GEMM_SMEM 131072

__device__ __forceinline__ void cpA(float* sA, const float* gA, int mt0, int c, int tid) {
#pragma unroll
    for (int i = 0; i < 8; i++) {
        int v = i * 256 + tid;
        int mt_l = v >> 8, rest = v & 255;
        const float* src = gA + (((size_t)(mt0 + mt_l) * 32 + c * 8 + (rest >> 5)) * 32 + (rest & 31)) * 4;
        cp16(smem_u32(sA + v * 4), src);
    }
}

__device__ __forceinline__ void cpB(float* sB, const float* gB, int c, int tid) {
#pragma unroll
    for (int i = 0; i < 8; i++) {
        int v = i * 256 + tid;
        int nt_l = v >> 7, r = v & 127;
        const float* src = gB + ((size_t)nt_l * 32 + c * 8 + (r >> 4)) * 64 + (r & 15) * 4;
        cp16(smem_u32(sB + v * 4), src);
    }
}

__device__ __forceinline__ void compute_chunk(const float* sA, const float* sB,
                                              float c[2][8][4], int wm, int wn, int lane) {
#pragma unroll
    for (int kt = 0; kt < 8; kt++) {
        float4 a0 = *(const float4*)(sA + ((size_t)((wm * 2 + 0) * 8 + kt) * 32 + lane) * 4);
        float4 a1 = *(const float4*)(sA + ((size_t)((wm * 2 + 1) * 8 + kt) * 32 + lane) * 4);
#pragma unroll
        for (int nn = 0; nn < 8; nn++) {
            float2 b = *(const float2*)(sB + ((size_t)((wn * 8 + nn) * 8 + kt) * 32 + lane) * 2);
            unsigned ub0 = __float_as_uint(b.x), ub1 = __float_as_uint(b.y);
            mma_tf32(c[0][nn], __float_as_uint(a0.x), __float_as_uint(a0.y),
                     __float_as_uint(a0.z), __float_as_uint(a0.w), ub0, ub1);
            mma_tf32(c[1][nn], __float_as_uint(a1.x), __float_as_uint(a1.y),
                     __float_as_uint(a1.z), __float_as_uint(a1.w), ub0, ub1);
        }
    }
}

__global__ void __launch_bounds__(256, 1) k_gemm() {
    extern __shared__ float sm[];
    float* A0 = sm;
    float* A1 = sm + 8192;
    float* B0 = sm + 16384;
    float* B1 = sm + 24576;

    int tid = threadIdx.x;
    int lane = tid & 31, warp = tid >> 5;
    int wm = warp & 3, wn = warp >> 2;
    int t = blockIdx.x >> 1, ntile = blockIdx.x & 1;
    int mt0 = blockIdx.y * 8;        // 8 m16-tiles = 128 rows
    int m0 = mt0 * 16, n0 = ntile * 128;

    const float* gA = g_hA;
    const float* gB = g_WtB + ((size_t)t * 32 + ntile * 16) * 32 * 64;

    float c[2][8][4];
#pragma unroll
    for (int mm = 0; mm < 2; mm++)
#pragma unroll
        for (int nn = 0; nn < 8; nn++)
#pragma unroll
            for (int q = 0; q < 4; q++) c[mm][nn][q] = 0.f;

    cpA(A0, gA, mt0, 0, tid); cpB(B0, gB, 0, tid); cp_commit();
    cpA(A1, gA, mt0, 1, tid); cpB(B1, gB, 1, tid); cp_commit();

    cp_wait1(); __syncthreads();
    compute_chunk(A0, B0, c, wm, wn, lane);
    __syncthreads();
    cpA(A0, gA, mt0, 2, tid); cpB(B0, gB, 2, tid); cp_commit();

    cp_wait1(); __syncthreads();
    compute_chunk(A1, B1, c, wm, wn, lane);
    __syncthreads();
    cpA(A1, gA, mt0, 3, tid); cpB(B1, gB, 3, tid); cp_commit();

    cp_wait1(); __syncthreads();
    compute_chunk(A0, B0, c, wm, wn, lane);

    cp_wait0(); __syncthreads();
    compute_chunk(A1, B1, c, wm, wn, lane);

    // epilogue -> g_Y
    int gid = lane >> 2, tig = lane & 3;
    float* Yb = g_Y + ((size_t)t * NN + m0) * CC + n0;
#pragma unroll
    for (int mm = 0; mm < 2; mm++) {
#pragma unroll
        for (int nn = 0; nn < 8; nn++) {
            int r = wm * 32 + mm * 16 + gid;
            int cc2 = wn * 64 + nn * 8 + tig * 2;
            *(float2*)(Yb + (size_t)r * CC + cc2) = make_float2(c[mm][nn][0], c[mm][nn][1]);
            *(float2*)(Yb + (size_t)(r + 8) * CC + cc2) = make_float2(c[mm][nn][2], c[mm][nn][3]);
        }
    }
}

// warp-per-node gather
__global__ void k_gather(const float* __restrict__ xbase, const float* __restrict__ W,
                         float* __restrict__ dout, const int* __restrict__ bid,
                         int final_pass) {
    int widx = (blockIdx.x * blockDim.x + threadIdx.x) >> 5;
    int lane = threadIdx.x & 31;
    if (widx >= NN) return;
    int n = widx;
    const float* bp;
    float* dst;
    if (final_pass) {
        bp = xbase + (size_t)n * CC;
        dst = dout + (size_t)n * CC;
    } else {
        bp = g_emb + (size_t)bid[n] * CC;
        dst = g_out1 + (size_t)n * CC;
    }
    float4 a0 = *(const float4*)(bp + lane * 8);
    float4 a1 = *(const float4*)(bp + lane * 8 + 4);
    int e0 = g_off[n], e1 = g_off[n + 1];
    for (int e = e0; e < e1; e++) {
        unsigned p = g_epack[e];
        int c = p & 0xFFFF;
        int t = (p >> 16) & 7;
        int nt = (p >> 19) & 7;
        const float* y = g_Y + ((size_t)t * NN + c) * CC + lane * 8;
        const float* wr = W + (size_t)(t * WROW + CC + nt) * CC + lane * 8;
        float4 y0 = *(const float4*)y;
        float4 y1 = *(const float4*)(y + 4);
        float4 w0 = *(const float4*)wr;
        float4 w1 = *(const float4*)(wr + 4);
        a0.x += y0.x + w0.x; a0.y += y0.y + w0.y;
        a0.z += y0.z + w0.z; a0.w += y0.w + w0.w;
        a1.x += y1.x + w1.x; a1.y += y1.y + w1.y;
        a1.z += y1.z + w1.z; a1.w += y1.w + w1.w;
    }
    *(float4*)(dst + lane * 8) = a0;
    *(float4*)(dst + lane * 8 + 4) = a1;
}

// ---------------- launcher ----------------
extern "C" void kernel_launch(void* const* d_in, const int* in_sizes, int n_in,
                              void* d_out, int out_size) {
    const float* x    = (const float*)d_in[0];
    const float* emb  = (const float*)d_in[1];
    const int*   bid  = (const int*)d_in[2];
    const int*   ei   = (const int*)d_in[3];
    const int*   et   = (const int*)d_in[4];
    const int*   ntp  = (const int*)d_in[5];
    const float* gn1w = (const float*)d_in[6];
    const float* gn1b = (const float*)d_in[7];
    const float* w1   = (const float*)d_in[8];
    const float* embw = (const float*)d_in[9];
    const float* embb = (const float*)d_in[10];
    const float* gn2w = (const float*)d_in[11];
    const float* gn2b = (const float*)d_in[12];
    const float* w2   = (const float*)d_in[13];
    float* out = (float*)d_out;

    static int s_attr = 0;
    if (!s_attr) {
        cudaFuncSetAttribute(k_gemm, cudaFuncAttributeMaxDynamicSharedMemorySize, GEMM_SMEM);
        s_attr = 1;
    }

    // CSR build (shared by both convs) + emb
    k_zero_all<<<(NN + 255) / 256, 256>>>();
    k_deg<<<EE / 256, 256>>>(ei);
    k_scan<<<1, 1024>>>();
    k_fill<<<EE / 256, 256>>>(ei, et, ntp);
    k_emb<<<BB, 256>>>(emb, embw, embb);

    // block 1
    k_stats<<<NN / 64, 256>>>(x, 0, bid, 1);
    k_fin<<<1, 256>>>();
    k_norm<<<NN / 16, 256>>>(x, 0, bid, gn1w, gn1b);
    k_wt<<<(NET * 32768 + 255) / 256, 256>>>(w1);
    k_gemm<<<dim3(14, NN / 128), 256, GEMM_SMEM>>>();
    k_gather<<<NN / 8, 256>>>(x, w1, out, bid, 0);

    // block 2
    k_zero_stats<<<8, 256>>>();
    k_stats<<<NN / 64, 256>>>(x, 1, bid, 0);
    k_fin<<<1, 256>>>();
    k_norm<<<NN / 16, 256>>>(x, 1, bid, gn2w, gn2b);
    k_wt<<<(NET * 32768 + 255) / 256, 256>>>(w2);
    k_gemm<<<dim3(14, NN / 128), 256, GEMM_SMEM>>>();
    k_gather<<<NN / 8, 256>>>(x, w2, out, bid, 1);
}

// round 5
// speedup vs baseline: 1.3716x; 1.3716x over previous
#include <cuda_runtime.h>
#include <cuda_fp16.h>
#include <cstdint>

// ---------------- problem constants ----------------
#define NN      65536
#define CC      256
#define BB      8
#define EMBD    512
#define NET     7
#define EE      458752
#define WROW    263
#define EPSV    1e-5f

// ---------------- device scratch ----------------
// A fp16 fragment layout: [mt(4096)][kt(16)][lane(32)][4 x half2]  (u32 words)
__device__ __align__(256) uint32_t g_hA[(size_t)NN * 16 * 32 * 4 / 8];   // NN*CC/2 u32
// B fp16 fragment layout: [t][nt(32)][kt(16)][lane(32)][2]  (u32 words)
__device__ __align__(256) uint32_t g_WtB[(size_t)NET * 32 * 16 * 32 * 2];
__device__ __align__(256) float    g_Y[(size_t)NET * NN * CC];
__device__ __align__(256) float    g_out1[(size_t)NN * CC];
__device__ float    g_S1[BB * CC];
__device__ float    g_S2[BB * CC];
__device__ float    g_cnt[BB];
__device__ float    g_mg[BB * 32];
__device__ float    g_istd[BB * 32];
__device__ __align__(256) float    g_emb[BB * CC];
__device__ int      g_deg[NN];
__device__ int      g_off[NN + 1];
__device__ int      g_cur[NN];
__device__ unsigned g_epack[EE];

// ---------------- helpers ----------------
__device__ __forceinline__ float silu(float y) {
    return y / (1.f + __expf(-y));
}

__device__ __forceinline__ uint32_t smem_u32(const void* p) {
    uint32_t a;
    asm("{ .reg .u64 t; cvta.to.shared.u64 t, %1; cvt.u32.u64 %0, t; }" : "=r"(a) : "l"(p));
    return a;
}

__device__ __forceinline__ void cp16(uint32_t dst, const void* src) {
    asm volatile("cp.async.cg.shared.global [%0], [%1], 16;\n" :: "r"(dst), "l"(src));
}
__device__ __forceinline__ void cp_commit() { asm volatile("cp.async.commit_group;\n" ::: "memory"); }
__device__ __forceinline__ void cp_wait1()  { asm volatile("cp.async.wait_group 1;\n" ::: "memory"); }
__device__ __forceinline__ void cp_wait0()  { asm volatile("cp.async.wait_group 0;\n" ::: "memory"); }

__device__ __forceinline__ void mma_f16(float c[4], uint32_t a0, uint32_t a1,
                                        uint32_t a2, uint32_t a3,
                                        uint32_t b0, uint32_t b1) {
    asm volatile(
        "mma.sync.aligned.m16n8k16.row.col.f32.f16.f16.f32 "
        "{%0,%1,%2,%3}, {%4,%5,%6,%7}, {%8,%9}, {%0,%1,%2,%3};\n"
        : "+f"(c[0]), "+f"(c[1]), "+f"(c[2]), "+f"(c[3])
        : "r"(a0), "r"(a1), "r"(a2), "r"(a3), "r"(b0), "r"(b1));
}

// ---------------- CSR / stats kernels ----------------

__global__ void k_zero_all() {
    int i = blockIdx.x * blockDim.x + threadIdx.x;
    if (i < NN)      g_deg[i] = 0;
    if (i < BB * CC) { g_S1[i] = 0.f; g_S2[i] = 0.f; }
    if (i < BB)      g_cnt[i] = 0.f;
}

__global__ void k_zero_stats() {
    int i = blockIdx.x * blockDim.x + threadIdx.x;
    if (i < BB * CC) { g_S1[i] = 0.f; g_S2[i] = 0.f; }
}

__global__ void k_deg(const int* __restrict__ ei) {
    int e = blockIdx.x * blockDim.x + threadIdx.x;
    if (e < EE) atomicAdd(&g_deg[ei[e]], 1);
}

__global__ void k_scan() {
    __shared__ int ps[1024];
    int t = threadIdx.x;
    int s = 0;
#pragma unroll 8
    for (int i = 0; i < 64; i++) s += g_deg[t * 64 + i];
    ps[t] = s;
    __syncthreads();
    for (int off = 1; off < 1024; off <<= 1) {
        int v = (t >= off) ? ps[t - off] : 0;
        __syncthreads();
        ps[t] += v;
        __syncthreads();
    }
    int run = (t == 0) ? 0 : ps[t - 1];
    for (int i = 0; i < 64; i++) {
        int d = g_deg[t * 64 + i];
        g_off[t * 64 + i] = run;
        g_cur[t * 64 + i] = run;
        run += d;
    }
    if (t == 1023) g_off[NN] = run;
}

__global__ void k_fill(const int* __restrict__ ei, const int* __restrict__ et,
                       const int* __restrict__ ntp) {
    int e = blockIdx.x * blockDim.x + threadIdx.x;
    if (e >= EE) return;
    int r = ei[e];
    int c = ei[EE + e];
    int t = et[e];
    int nt = ntp[c];
    int pos = atomicAdd(&g_cur[r], 1);
    g_epack[pos] = (unsigned)c | ((unsigned)t << 16) | ((unsigned)nt << 19);
}

__global__ void k_emb(const float* __restrict__ emb, const float* __restrict__ ew,
                      const float* __restrict__ eb) {
    __shared__ float se[EMBD];
    int b = blockIdx.x;
    int j = threadIdx.x;
    for (int k = j; k < EMBD; k += 256) se[k] = silu(emb[b * EMBD + k]);
    __syncthreads();
    float acc = eb[j];
#pragma unroll 8
    for (int k = 0; k < EMBD; k++) acc = fmaf(se[k], ew[k * CC + j], acc);
    g_emb[b * CC + j] = acc;
}

__global__ void k_stats(const float* __restrict__ src, int use_out1,
                        const int* __restrict__ bid, int do_cnt) {
    const float* s = use_out1 ? g_out1 : src;
    int c = threadIdx.x;
    int r0 = blockIdx.x * 64;
    float s1 = 0.f, s2 = 0.f;
    int cb = bid[r0];
    int cl = 0;
    for (int i = 0; i < 64; i++) {
        int r = r0 + i;
        int b = bid[r];
        if (b != cb) {
            atomicAdd(&g_S1[cb * CC + c], s1);
            atomicAdd(&g_S2[cb * CC + c], s2);
            if (do_cnt && c == 0) atomicAdd(&g_cnt[cb], (float)cl);
            s1 = 0.f; s2 = 0.f; cl = 0; cb = b;
        }
        float v = s[(size_t)r * CC + c];
        s1 += v;
        s2 = fmaf(v, v, s2);
        cl++;
    }
    atomicAdd(&g_S1[cb * CC + c], s1);
    atomicAdd(&g_S2[cb * CC + c], s2);
    if (do_cnt && c == 0) atomicAdd(&g_cnt[cb], (float)cl);
}

__global__ void k_fin() {
    int t = threadIdx.x;
    int b = t >> 5, g = t & 31;
    float gs1 = 0.f, gs2 = 0.f;
#pragma unroll
    for (int i = 0; i < 8; i++) {
        gs1 += g_S1[b * CC + g * 8 + i];
        gs2 += g_S2[b * CC + g * 8 + i];
    }
    float n = g_cnt[b] * 8.f;
    float inv = 1.f / (n + EPSV);
    float m = gs1 * inv;
    float var = (gs2 - 2.f * m * gs1 + n * m * m) * inv;
    g_mg[b * 32 + g] = m;
    g_istd[b * 32 + g] = rsqrtf(var + EPSV);
}

// norm + silu -> fp16 A-fragment layout (m16n8k16).
// block = m-tile of 16 rows, 256 threads. slot decode:
//   slot = ((kt)*32 + lane)*4 + reg ; reg = hi_r + 2*hi_c
//   row  = (reg&1)*8 + (lane>>2)
//   col0 = kt*16 + (reg>>1)*8 + (lane&3)*2 ; col1 = col0+1
__global__ void k_norm(const float* __restrict__ src, int use_out1,
                       const int* __restrict__ bid, const float* __restrict__ w,
                       const float* __restrict__ bbv) {
    __shared__ float s[16 * 256];
    __shared__ int   rb[16];
    const float* sp = use_out1 ? g_out1 : src;
    int mt = blockIdx.x;
    int tid = threadIdx.x;

#pragma unroll
    for (int j = 0; j < 4; j++) {
        int q = j * 256 + tid;
        int row = q >> 6, cv = (q & 63) * 4;
        *(float4*)&s[row * 256 + cv] = *(const float4*)(sp + (size_t)(mt * 16 + row) * CC + cv);
    }
    if (tid < 16) rb[tid] = bid[mt * 16 + tid];
    __syncthreads();

#pragma unroll
    for (int it = 0; it < 8; it++) {
        int slot = it * 256 + tid;                 // 0..2047
        int reg = slot & 3;
        int lane = (slot >> 2) & 31;
        int kt = slot >> 7;                        // 0..15
        int r = (reg & 1) * 8 + (lane >> 2);
        int c0 = kt * 16 + (reg >> 1) * 8 + (lane & 3) * 2;
        int b = rb[r];
        int g = c0 >> 3;
        float m = g_mg[b * 32 + g];
        float is = g_istd[b * 32 + g];
        float v0 = silu((s[r * 256 + c0]     - m) * is * w[c0]     + bbv[c0]);
        float v1 = silu((s[r * 256 + c0 + 1] - m) * is * w[c0 + 1] + bbv[c0 + 1]);
        __half2 h2 = __floats2half2_rn(v0, v1);
        g_hA[(((size_t)mt * 16 + kt) * 32 + lane) * 4 + reg] = *(uint32_t*)&h2;
    }
}

// W[t][k][n] -> fp16 B-fragment layout: [t][nt][kt][lane][2] u32
//   k = kt*16 + (lane&3)*2 + breg*8 (+1 in hi half) ; n = nt*8 + (lane>>2)
__global__ void k_wt(const float* __restrict__ W) {
    int g = blockIdx.x * blockDim.x + threadIdx.x;
    if (g >= NET * 32 * 16 * 32 * 2) return;
    int breg = g & 1;
    int lane = (g >> 1) & 31;
    int kt = (g >> 6) & 15;
    int nt = (g >> 10) & 31;
    int t = g >> 15;
    int k = kt * 16 + (lane & 3) * 2 + breg * 8;
    int n = nt * 8 + (lane >> 2);
    float v0 = W[(size_t)(t * WROW + k) * CC + n];
    float v1 = W[(size_t)(t * WROW + k + 1) * CC + n];
    __half2 h2 = __floats2half2_rn(v0, v1);
    g_WtB[(size_t)g] = *(uint32_t*)&h2;
}

// -------- fp16 mma.sync GEMM, fragment-major smem, cp.async double buffer ----
// CTA 128x128, K=256 in four K=64 chunks (4 k16-steps each).
// smem: A0|A1|B0|B1 each 16KB -> 64KB total -> 2 CTAs/SM.
#define GEMM_SMEM 65536

__device__ __forceinline__ void cpA(uint32_t* sA, int mt0, int c, int tid) {
#pragma unroll
    for (int i = 0; i < 4; i++) {
        int idx = i * 256 + tid;                   // 0..1023 16B units
        int mt_l = idx >> 7, rest = idx & 127;
        const uint32_t* src = g_hA + (((size_t)(mt0 + mt_l) * 16 + c * 4 + (rest >> 5)) * 32 + (rest & 31)) * 4;
        cp16(smem_u32(sA + idx * 4), src);
    }
}

__device__ __forceinline__ void cpB(uint32_t* sB, const uint32_t* gB, int c, int tid) {
#pragma unroll
    for (int i = 0; i < 4; i++) {
        int idx = i * 256 + tid;                   // 0..1023 16B units
        int nt = idx >> 6, rest = idx & 63;
        int ktl = rest >> 4, u = rest & 15;
        const uint32_t* src = gB + ((size_t)nt * 16 + c * 4 + ktl) * 64 + u * 4;
        cp16(smem_u32(sB + ((nt * 4 + ktl) * 64 + u * 4)), src);
    }
}

__device__ __forceinline__ void compute_chunk(const uint32_t* sA, const uint32_t* sB,
                                              float c[2][8][4], int wm, int wn, int lane) {
#pragma unroll
    for (int ktl = 0; ktl < 4; ktl++) {
        uint4 a0 = *(const uint4*)(sA + ((wm * 2 + 0) * 4 + ktl) * 128 + lane * 4);
        uint4 a1 = *(const uint4*)(sA + ((wm * 2 + 1) * 4 + ktl) * 128 + lane * 4);
#pragma unroll
        for (int nn = 0; nn < 8; nn++) {
            uint2 b = *(const uint2*)(sB + ((wn * 8 + nn) * 4 + ktl) * 64 + lane * 2);
            mma_f16(c[0][nn], a0.x, a0.y, a0.z, a0.w, b.x, b.y);
            mma_f16(c[1][nn], a1.x, a1.y, a1.z, a1.w, b.x, b.y);
        }
    }
}

__global__ void __launch_bounds__(256, 2) k_gemm() {
    extern __shared__ uint32_t sm[];
    uint32_t* A0 = sm;
    uint32_t* A1 = sm + 4096;
    uint32_t* B0 = sm + 8192;
    uint32_t* B1 = sm + 12288;

    int tid = threadIdx.x;
    int lane = tid & 31, warp = tid >> 5;
    int wm = warp & 3, wn = warp >> 2;
    int t = blockIdx.x >> 1, ntile = blockIdx.x & 1;
    int mt0 = blockIdx.y * 8;
    int m0 = mt0 * 16, n0 = ntile * 128;

    const uint32_t* gB = g_WtB + ((size_t)t * 32 + ntile * 16) * 16 * 64;

    float c[2][8][4];
#pragma unroll
    for (int mm = 0; mm < 2; mm++)
#pragma unroll
        for (int nn = 0; nn < 8; nn++)
#pragma unroll
            for (int q = 0; q < 4; q++) c[mm][nn][q] = 0.f;

    cpA(A0, mt0, 0, tid); cpB(B0, gB, 0, tid); cp_commit();
    cpA(A1, mt0, 1, tid); cpB(B1, gB, 1, tid); cp_commit();

    cp_wait1(); __syncthreads();
    compute_chunk(A0, B0, c, wm, wn, lane);
    __syncthreads();
    cpA(A0, mt0, 2, tid); cpB(B0, gB, 2, tid); cp_commit();

    cp_wait1(); __syncthreads();
    compute_chunk(A1, B1, c, wm, wn, lane);
    __syncthreads();
    cpA(A1, mt0, 3, tid); cpB(B1, gB, 3, tid); cp_commit();

    cp_wait1(); __syncthreads();
    compute_chunk(A0, B0, c, wm, wn, lane);

    cp_wait0(); __syncthreads();
    compute_chunk(A1, B1, c, wm, wn, lane);

    // epilogue -> g_Y (C fragment layout of m16n8k16 == m16n8k8)
    int gid = lane >> 2, tig = lane & 3;
    float* Yb = g_Y + ((size_t)t * NN + m0) * CC + n0;
#pragma unroll
    for (int mm = 0; mm < 2; mm++) {
#pragma unroll
        for (int nn = 0; nn < 8; nn++) {
            int r = wm * 32 + mm * 16 + gid;
            int cc2 = wn * 64 + nn * 8 + tig * 2;
            *(float2*)(Yb + (size_t)r * CC + cc2) = make_float2(c[mm][nn][0], c[mm][nn][1]);
            *(float2*)(Yb + (size_t)(r + 8) * CC + cc2) = make_float2(c[mm][nn][2], c[mm][nn][3]);
        }
    }
}

// warp-per-node gather
__global__ void k_gather(const float* __restrict__ xbase, const float* __restrict__ W,
                         float* __restrict__ dout, const int* __restrict__ bid,
                         int final_pass) {
    int widx = (blockIdx.x * blockDim.x + threadIdx.x) >> 5;
    int lane = threadIdx.x & 31;
    if (widx >= NN) return;
    int n = widx;
    const float* bp;
    float* dst;
    if (final_pass) {
        bp = xbase + (size_t)n * CC;
        dst = dout + (size_t)n * CC;
    } else {
        bp = g_emb + (size_t)bid[n] * CC;
        dst = g_out1 + (size_t)n * CC;
    }
    float4 a0 = *(const float4*)(bp + lane * 8);
    float4 a1 = *(const float4*)(bp + lane * 8 + 4);
    int e0 = g_off[n], e1 = g_off[n + 1];
    for (int e = e0; e < e1; e++) {
        unsigned p = g_epack[e];
        int c = p & 0xFFFF;
        int t = (p >> 16) & 7;
        int nt = (p >> 19) & 7;
        const float* y = g_Y + ((size_t)t * NN + c) * CC + lane * 8;
        const float* wr = W + (size_t)(t * WROW + CC + nt) * CC + lane * 8;
        float4 y0 = *(const float4*)y;
        float4 y1 = *(const float4*)(y + 4);
        float4 w0 = *(const float4*)wr;
        float4 w1 = *(const float4*)(wr + 4);
        a0.x += y0.x + w0.x; a0.y += y0.y + w0.y;
        a0.z += y0.z + w0.z; a0.w += y0.w + w0.w;
        a1.x += y1.x + w1.x; a1.y += y1.y + w1.y;
        a1.z += y1.z + w1.z; a1.w += y1.w + w1.w;
    }
    *(float4*)(dst + lane * 8) = a0;
    *(float4*)(dst + lane * 8 + 4) = a1;
}

// ---------------- launcher ----------------
extern "C" void kernel_launch(void* const* d_in, const int* in_sizes, int n_in,
                              void* d_out, int out_size) {
    const float* x    = (const float*)d_in[0];
    const float* emb  = (const float*)d_in[1];
    const int*   bid  = (const int*)d_in[2];
    const int*   ei   = (const int*)d_in[3];
    const int*   et   = (const int*)d_in[4];
    const int*   ntp  = (const int*)d_in[5];
    const float* gn1w = (const float*)d_in[6];
    const float* gn1b = (const float*)d_in[7];
    const float* w1   = (const float*)d_in[8];
    const float* embw = (const float*)d_in[9];
    const float* embb = (const float*)d_in[10];
    const float* gn2w = (const float*)d_in[11];
    const float* gn2b = (const float*)d_in[12];
    const float* w2   = (const float*)d_in[13];
    float* out = (float*)d_out;

    static int s_attr = 0;
    if (!s_attr) {
        cudaFuncSetAttribute(k_gemm, cudaFuncAttributeMaxDynamicSharedMemorySize, GEMM_SMEM);
        s_attr = 1;
    }

    // CSR build (shared by both convs) + emb
    k_zero_all<<<(NN + 255) / 256, 256>>>();
    k_deg<<<EE / 256, 256>>>(ei);
    k_scan<<<1, 1024>>>();
    k_fill<<<EE / 256, 256>>>(ei, et, ntp);
    k_emb<<<BB, 256>>>(emb, embw, embb);

    // block 1
    k_stats<<<NN / 64, 256>>>(x, 0, bid, 1);
    k_fin<<<1, 256>>>();
    k_norm<<<NN / 16, 256>>>(x, 0, bid, gn1w, gn1b);
    k_wt<<<NET * 32 * 16 * 32 * 2 / 256, 256>>>(w1);
    k_gemm<<<dim3(14, NN / 128), 256, GEMM_SMEM>>>();
    k_gather<<<NN / 8, 256>>>(x, w1, out, bid, 0);

    // block 2
    k_zero_stats<<<8, 256>>>();
    k_stats<<<NN / 64, 256>>>(x, 1, bid, 0);
    k_fin<<<1, 256>>>();
    k_norm<<<NN / 16, 256>>>(x, 1, bid, gn2w, gn2b);
    k_wt<<<NET * 32 * 16 * 32 * 2 / 256, 256>>>(w2);
    k_gemm<<<dim3(14, NN / 128), 256, GEMM_SMEM>>>();
    k_gather<<<NN / 8, 256>>>(x, w2, out, bid, 1);
}